// round 1
// baseline (speedup 1.0000x reference)
#include <cuda_runtime.h>

// Problem constants
#define NB   32      // batch
#define HW   48      // height = width
#define DIM  384
#define D3   1152
#define NHE  8
#define HDI  48
#define WSZ  6
#define NWIN 64      // windows per image (8x8)
#define VTOK 36      // tokens per window
#define NM   2048    // NB * NWIN
#define TOK  73728   // NM * VTOK
#define SCALE 0.14433756729740643f  // 48^-0.5

// Scratch (device globals: allocation-guard-safe)
__device__ float g_qkv[(size_t)TOK * D3];   // ~340 MB
__device__ float g_att[(size_t)TOK * DIM];  // ~113 MB

// Token row -> source/destination pixel offset (in floats).
// roll(-3) gather and roll(+3) scatter use the SAME (i+3)%48 mapping.
__device__ __forceinline__ int token_px_offset(int mr) {
    int m  = mr / VTOK;
    int t  = mr - m * VTOK;
    int b  = m >> 6;
    int wi = m & 63;
    int i  = (wi >> 3) * WSZ + t / WSZ;
    int j  = (wi & 7)  * WSZ + t - (t / WSZ) * WSZ;
    int h  = (i < 45) ? i + 3 : i - 45;
    int w  = (j < 45) ? j + 3 : j - 45;
    return ((b * HW + h) * HW + w) * DIM;
}

// ---------------------------------------------------------------------------
// Kernel 1: fused roll+window-gather + QKV GEMM  (73728x1152 = A(73728x384) @ W(384x1152))
// 128x128x16 tiles, 256 threads, 8x8 microtiles.
// ---------------------------------------------------------------------------
__global__ __launch_bounds__(256) void qkv_gemm(const float* __restrict__ x,
                                                const float* __restrict__ wq,
                                                const float* __restrict__ bq) {
    const int r0 = blockIdx.x * 128;
    const int n0 = blockIdx.y * 128;
    __shared__ float As[16][132];   // padded: conflict-free transposed store
    __shared__ float Bs[16][128];
    __shared__ int   rowoff[128];

    const int tid = threadIdx.x;
    if (tid < 128) rowoff[tid] = token_px_offset(r0 + tid);
    __syncthreads();

    const int tx = tid & 15;   // N dir
    const int ty = tid >> 4;   // M dir
    float acc[8][8] = {};

    for (int k0 = 0; k0 < DIM; k0 += 16) {
        #pragma unroll
        for (int i = 0; i < 2; i++) {          // A tile: 512 float4
            int fid = tid + i * 256;
            int r = fid >> 2;
            int c = (fid & 3) * 4;
            float4 va = *(const float4*)(x + rowoff[r] + k0 + c);
            As[c + 0][r] = va.x; As[c + 1][r] = va.y;
            As[c + 2][r] = va.z; As[c + 3][r] = va.w;
        }
        #pragma unroll
        for (int i = 0; i < 2; i++) {          // B tile: 512 float4
            int fid = tid + i * 256;
            int kk = fid >> 5;
            int c  = (fid & 31) * 4;
            *(float4*)&Bs[kk][c] = *(const float4*)(wq + (size_t)(k0 + kk) * D3 + n0 + c);
        }
        __syncthreads();
        #pragma unroll
        for (int kk = 0; kk < 16; kk++) {
            float a[8], b[8];
            *(float4*)&a[0] = *(float4*)&As[kk][ty * 8];
            *(float4*)&a[4] = *(float4*)&As[kk][ty * 8 + 4];
            *(float4*)&b[0] = *(float4*)&Bs[kk][tx * 8];
            *(float4*)&b[4] = *(float4*)&Bs[kk][tx * 8 + 4];
            #pragma unroll
            for (int i2 = 0; i2 < 8; i2++)
                #pragma unroll
                for (int j2 = 0; j2 < 8; j2++)
                    acc[i2][j2] += a[i2] * b[j2];
        }
        __syncthreads();
    }

    float bias[8];
    #pragma unroll
    for (int j2 = 0; j2 < 8; j2++) bias[j2] = bq[n0 + tx * 8 + j2];

    #pragma unroll
    for (int i2 = 0; i2 < 8; i2++) {
        float* cp = g_qkv + (size_t)(r0 + ty * 8 + i2) * D3 + n0 + tx * 8;
        #pragma unroll
        for (int j2 = 0; j2 < 8; j2 += 4) {
            float4 o;
            o.x = acc[i2][j2 + 0] + bias[j2 + 0];
            o.y = acc[i2][j2 + 1] + bias[j2 + 1];
            o.z = acc[i2][j2 + 2] + bias[j2 + 2];
            o.w = acc[i2][j2 + 3] + bias[j2 + 3];
            *(float4*)(cp + j2) = o;
        }
    }
}

// ---------------------------------------------------------------------------
// Kernel 2: per-(window, head) masked attention. Mask regions computed
// analytically (tokens attend iff same Swin shift-region).
// ---------------------------------------------------------------------------
__global__ __launch_bounds__(128) void attn_kernel() {
    const int m    = blockIdx.x;
    const int head = blockIdx.y;
    __shared__ float qs[VTOK][HDI];
    __shared__ float ks[VTOK][HDI];
    __shared__ float vs[VTOK][HDI];
    __shared__ float ss[VTOK][VTOK];
    __shared__ int   rid[VTOK];

    const int tid = threadIdx.x;
    const float* base = g_qkv + (size_t)m * VTOK * D3 + head * HDI;

    // load Q,K,V  (3 * 36 * 12 float4)
    for (int idx = tid; idx < 3 * VTOK * 12; idx += 128) {
        int t3  = idx / (VTOK * 12);
        int rem = idx - t3 * (VTOK * 12);
        int r = rem / 12;
        int c = rem - r * 12;
        float4 f = *(const float4*)(base + t3 * DIM + (size_t)r * D3 + c * 4);
        float* dst = (t3 == 0) ? &qs[r][c * 4] : (t3 == 1) ? &ks[r][c * 4] : &vs[r][c * 4];
        *(float4*)dst = f;
    }
    if (tid < VTOK) {
        int wi = m & 63;
        int i  = (wi >> 3) * WSZ + tid / WSZ;
        int j  = (wi & 7)  * WSZ + tid % WSZ;
        rid[tid] = ((i < 45) ? 2 : 0) + ((j < 45) ? 1 : 0);
    }
    __syncthreads();

    // S = Q K^T * scale, masked
    for (int idx = tid; idx < VTOK * VTOK; idx += 128) {
        int v = idx / VTOK;
        int u = idx - v * VTOK;
        float acc = 0.f;
        #pragma unroll
        for (int c = 0; c < 12; c++) {
            float4 a = *(float4*)&qs[v][c * 4];
            float4 b = *(float4*)&ks[u][c * 4];
            acc += a.x * b.x + a.y * b.y + a.z * b.z + a.w * b.w;
        }
        ss[v][u] = (rid[v] == rid[u]) ? acc * SCALE : -1e30f;
    }
    __syncthreads();

    // row softmax (one thread per row)
    if (tid < VTOK) {
        float mx = -1e30f;
        #pragma unroll
        for (int u = 0; u < VTOK; u++) mx = fmaxf(mx, ss[tid][u]);
        float sum = 0.f;
        #pragma unroll
        for (int u = 0; u < VTOK; u++) {
            float e = __expf(ss[tid][u] - mx);
            ss[tid][u] = e;
            sum += e;
        }
        float inv = 1.f / sum;
        #pragma unroll
        for (int u = 0; u < VTOK; u++) ss[tid][u] *= inv;
    }
    __syncthreads();

    // O = P V  -> g_att[(m*36+v)*384 + head*48 + d]
    for (int idx = tid; idx < VTOK * 12; idx += 128) {
        int v = idx / 12;
        int c = idx - v * 12;
        float4 acc = make_float4(0.f, 0.f, 0.f, 0.f);
        #pragma unroll
        for (int u = 0; u < VTOK; u++) {
            float  p  = ss[v][u];
            float4 vv = *(float4*)&vs[u][c * 4];
            acc.x += p * vv.x; acc.y += p * vv.y;
            acc.z += p * vv.z; acc.w += p * vv.w;
        }
        *(float4*)(g_att + (size_t)(m * VTOK + v) * DIM + head * HDI + c * 4) = acc;
    }
}

// ---------------------------------------------------------------------------
// Kernel 3: Proj GEMM (73728x384 @ 384x384) + bias + window-reverse/roll scatter
// ---------------------------------------------------------------------------
__global__ __launch_bounds__(256) void proj_gemm(const float* __restrict__ wp,
                                                 const float* __restrict__ bp,
                                                 float* __restrict__ out) {
    const int r0 = blockIdx.x * 128;
    const int n0 = blockIdx.y * 128;
    __shared__ float As[16][132];
    __shared__ float Bs[16][128];
    __shared__ int   outoff[128];

    const int tid = threadIdx.x;
    if (tid < 128) outoff[tid] = token_px_offset(r0 + tid);
    __syncthreads();

    const int tx = tid & 15;
    const int ty = tid >> 4;
    float acc[8][8] = {};

    for (int k0 = 0; k0 < DIM; k0 += 16) {
        #pragma unroll
        for (int i = 0; i < 2; i++) {
            int fid = tid + i * 256;
            int r = fid >> 2;
            int c = (fid & 3) * 4;
            float4 va = *(const float4*)(g_att + (size_t)(r0 + r) * DIM + k0 + c);
            As[c + 0][r] = va.x; As[c + 1][r] = va.y;
            As[c + 2][r] = va.z; As[c + 3][r] = va.w;
        }
        #pragma unroll
        for (int i = 0; i < 2; i++) {
            int fid = tid + i * 256;
            int kk = fid >> 5;
            int c  = (fid & 31) * 4;
            *(float4*)&Bs[kk][c] = *(const float4*)(wp + (size_t)(k0 + kk) * DIM + n0 + c);
        }
        __syncthreads();
        #pragma unroll
        for (int kk = 0; kk < 16; kk++) {
            float a[8], b[8];
            *(float4*)&a[0] = *(float4*)&As[kk][ty * 8];
            *(float4*)&a[4] = *(float4*)&As[kk][ty * 8 + 4];
            *(float4*)&b[0] = *(float4*)&Bs[kk][tx * 8];
            *(float4*)&b[4] = *(float4*)&Bs[kk][tx * 8 + 4];
            #pragma unroll
            for (int i2 = 0; i2 < 8; i2++)
                #pragma unroll
                for (int j2 = 0; j2 < 8; j2++)
                    acc[i2][j2] += a[i2] * b[j2];
        }
        __syncthreads();
    }

    float bias[8];
    #pragma unroll
    for (int j2 = 0; j2 < 8; j2++) bias[j2] = bp[n0 + tx * 8 + j2];

    #pragma unroll
    for (int i2 = 0; i2 < 8; i2++) {
        float* cp = out + (size_t)outoff[ty * 8 + i2] + n0 + tx * 8;
        #pragma unroll
        for (int j2 = 0; j2 < 8; j2 += 4) {
            float4 o;
            o.x = acc[i2][j2 + 0] + bias[j2 + 0];
            o.y = acc[i2][j2 + 1] + bias[j2 + 1];
            o.z = acc[i2][j2 + 2] + bias[j2 + 2];
            o.w = acc[i2][j2 + 3] + bias[j2 + 3];
            *(float4*)(cp + j2) = o;
        }
    }
}

extern "C" void kernel_launch(void* const* d_in, const int* in_sizes, int n_in,
                              void* d_out, int out_size) {
    const float* x      = (const float*)d_in[0];
    const float* w_qkv  = (const float*)d_in[1];
    const float* b_qkv  = (const float*)d_in[2];
    const float* w_proj = (const float*)d_in[3];
    const float* b_proj = (const float*)d_in[4];
    float* out = (float*)d_out;

    qkv_gemm<<<dim3(TOK / 128, D3 / 128), 256>>>(x, w_qkv, b_qkv);
    attn_kernel<<<dim3(NM, NHE), 128>>>();
    proj_gemm<<<dim3(TOK / 128, DIM / 128), 256>>>(w_proj, b_proj, out);
}

// round 2
// speedup vs baseline: 1.6174x; 1.6174x over previous
#include <cuda_runtime.h>
#include <cuda_bf16.h>
#include <cstdint>

#define NB   32
#define HW   48
#define DIM  384
#define D3   1152
#define NHE  8
#define HDI  48
#define WSZ  6
#define VTOK 36
#define NM   2048
#define TOK  73728
#define KDIM 384
#define SCALE 0.14433756729740643f

// ---------------- scratch (device globals; allocation-guard safe) ----------
__device__ __nv_bfloat16 g_x_hi[(size_t)TOK * KDIM];
__device__ __nv_bfloat16 g_x_lo[(size_t)TOK * KDIM];
__device__ __nv_bfloat16 g_wq_hi[(size_t)D3 * KDIM];   // transposed [n][k]
__device__ __nv_bfloat16 g_wq_lo[(size_t)D3 * KDIM];
__device__ __nv_bfloat16 g_wp_hi[(size_t)DIM * KDIM];  // transposed [n][k]
__device__ __nv_bfloat16 g_wp_lo[(size_t)DIM * KDIM];
__device__ float         g_qkv[(size_t)TOK * D3];      // raster pixel order
__device__ __nv_bfloat16 g_att_hi[(size_t)TOK * DIM];  // raster pixel order
__device__ __nv_bfloat16 g_att_lo[(size_t)TOK * DIM];

__device__ __forceinline__ void split2(float v, uint16_t& h, uint16_t& l) {
    __nv_bfloat16 hb = __float2bfloat16_rn(v);
    float r = v - __bfloat162float(hb);
    __nv_bfloat16 lb = __float2bfloat16_rn(r);
    h = __bfloat16_as_ushort(hb);
    l = __bfloat16_as_ushort(lb);
}

// ---------------- prep: split x into hi/lo bf16 ----------------------------
__global__ __launch_bounds__(256) void split_x(const float* __restrict__ x) {
    size_t i = (size_t)blockIdx.x * 256 + threadIdx.x;  // float4 index
    float4 v = ((const float4*)x)[i];
    uint16_t h0, h1, h2, h3, l0, l1, l2, l3;
    split2(v.x, h0, l0); split2(v.y, h1, l1);
    split2(v.z, h2, l2); split2(v.w, h3, l3);
    uint2 H, L;
    H.x = (uint32_t)h0 | ((uint32_t)h1 << 16);
    H.y = (uint32_t)h2 | ((uint32_t)h3 << 16);
    L.x = (uint32_t)l0 | ((uint32_t)l1 << 16);
    L.y = (uint32_t)l2 | ((uint32_t)l3 << 16);
    ((uint2*)g_x_hi)[i] = H;
    ((uint2*)g_x_lo)[i] = L;
}

// ---------------- prep: split + transpose weights ---------------------------
template <int NT>
__global__ __launch_bounds__(256) void split_w(const float* __restrict__ w) {
    int idx = blockIdx.x * 256 + threadIdx.x;       // idx = k*NT + n
    int k = idx / NT, n = idx - k * NT;
    uint16_t h, l;
    split2(w[idx], h, l);
    __nv_bfloat16* wh = (NT == D3) ? g_wq_hi : g_wp_hi;
    __nv_bfloat16* wl = (NT == D3) ? g_wq_lo : g_wp_lo;
    ((uint16_t*)wh)[(size_t)n * KDIM + k] = h;
    ((uint16_t*)wl)[(size_t)n * KDIM + k] = l;
}

// ---------------- bf16-split tensor-core GEMM -------------------------------
// C[M x NT] = A[M x 384] * B^T (B stored [NT][384]) + bias
// 128x128x32 tiles, 256 threads (8 warps as 2Mx4N, warp tile 64x32),
// mma.sync.m16n8k16.bf16, cp.async double buffering.
#define SSTRIDE 40        // bf16 elements per smem row (32 data + 8 pad)
#define TILE_B  10240     // 128*40*2 bytes
#define STAGE_B 40960

__device__ __forceinline__ void cp16(uint32_t dst, const void* src) {
    asm volatile("cp.async.cg.shared.global [%0], [%1], 16;\n" :: "r"(dst), "l"(src));
}

#define MMA_BF16(d, a, b)                                                     \
    asm volatile(                                                             \
        "mma.sync.aligned.m16n8k16.row.col.f32.bf16.bf16.f32 "                \
        "{%0,%1,%2,%3},{%4,%5,%6,%7},{%8,%9},{%0,%1,%2,%3};"                  \
        : "+f"(d[0]), "+f"(d[1]), "+f"(d[2]), "+f"(d[3])                      \
        : "r"(a[0]), "r"(a[1]), "r"(a[2]), "r"(a[3]), "r"(b[0]), "r"(b[1]))

__device__ __forceinline__ void stage_load(
    uint32_t sb, const __nv_bfloat16* __restrict__ Ah, const __nv_bfloat16* __restrict__ Al,
    const __nv_bfloat16* __restrict__ Bh, const __nv_bfloat16* __restrict__ Bl,
    int row0, int col0, int k0, int tid)
{
#pragma unroll
    for (int h2 = 0; h2 < 2; h2++) {
        int c = tid + h2 * 256;
        int r = c >> 2;
        int eo = (c & 3) * 8;                       // element offset in row
        uint32_t doff = (uint32_t)(r * SSTRIDE + eo) * 2;
        size_t aoff = (size_t)(row0 + r) * KDIM + k0 + eo;
        size_t boff = (size_t)(col0 + r) * KDIM + k0 + eo;
        cp16(sb + 0 * TILE_B + doff, Ah + aoff);
        cp16(sb + 1 * TILE_B + doff, Al + aoff);
        cp16(sb + 2 * TILE_B + doff, Bh + boff);
        cp16(sb + 3 * TILE_B + doff, Bl + boff);
    }
}

// WHICH: 0 = qkv (A=g_x, B=g_wq, C=g_qkv, NT=1152), 1 = proj (A=g_att, B=g_wp, C=out, NT=384)
template <int WHICH>
__global__ __launch_bounds__(256, 1) void gemm_bf16(const float* __restrict__ bias,
                                                    float* __restrict__ Cout)
{
    constexpr int NT = (WHICH == 0) ? D3 : DIM;
    const __nv_bfloat16* Ah = (WHICH == 0) ? g_x_hi : g_att_hi;
    const __nv_bfloat16* Al = (WHICH == 0) ? g_x_lo : g_att_lo;
    const __nv_bfloat16* Bh = (WHICH == 0) ? g_wq_hi : g_wp_hi;
    const __nv_bfloat16* Bl = (WHICH == 0) ? g_wq_lo : g_wp_lo;
    float* C = (WHICH == 0) ? g_qkv : Cout;

    extern __shared__ char sm[];
    const int tid  = threadIdx.x;
    const int row0 = blockIdx.x * 128;
    const int col0 = blockIdx.y * 128;
    const int lane = tid & 31, warp = tid >> 5;
    const int wm = warp & 1, wn = warp >> 1;      // 2 x 4 warp grid
    const int g = lane >> 2, t = lane & 3;

    uint32_t sbase = (uint32_t)__cvta_generic_to_shared(sm);

    float acc[4][4][4] = {};

    stage_load(sbase, Ah, Al, Bh, Bl, row0, col0, 0, tid);
    asm volatile("cp.async.commit_group;\n" ::: "memory");

    for (int kt = 0; kt < 12; kt++) {
        if (kt < 11) {
            stage_load(sbase + ((kt + 1) & 1) * STAGE_B, Ah, Al, Bh, Bl,
                       row0, col0, (kt + 1) * 32, tid);
            asm volatile("cp.async.commit_group;\n" ::: "memory");
            asm volatile("cp.async.wait_group 1;\n" ::: "memory");
        } else {
            asm volatile("cp.async.wait_group 0;\n" ::: "memory");
        }
        __syncthreads();

        const __nv_bfloat16* sA_h = (const __nv_bfloat16*)(sm + (kt & 1) * STAGE_B);
        const __nv_bfloat16* sA_l = sA_h + 5120;
        const __nv_bfloat16* sB_h = sA_h + 10240;
        const __nv_bfloat16* sB_l = sA_h + 15360;

#pragma unroll
        for (int k16 = 0; k16 < 32; k16 += 16) {
            uint32_t ah[4][4], al[4][4], bh[4][2], bl[4][2];
#pragma unroll
            for (int mt = 0; mt < 4; mt++) {
                int e = (wm * 64 + mt * 16 + g) * SSTRIDE + k16 + t * 2;
                ah[mt][0] = *(const uint32_t*)(sA_h + e);
                ah[mt][1] = *(const uint32_t*)(sA_h + e + 8 * SSTRIDE);
                ah[mt][2] = *(const uint32_t*)(sA_h + e + 8);
                ah[mt][3] = *(const uint32_t*)(sA_h + e + 8 * SSTRIDE + 8);
                al[mt][0] = *(const uint32_t*)(sA_l + e);
                al[mt][1] = *(const uint32_t*)(sA_l + e + 8 * SSTRIDE);
                al[mt][2] = *(const uint32_t*)(sA_l + e + 8);
                al[mt][3] = *(const uint32_t*)(sA_l + e + 8 * SSTRIDE + 8);
            }
#pragma unroll
            for (int nt = 0; nt < 4; nt++) {
                int e = (wn * 32 + nt * 8 + g) * SSTRIDE + k16 + t * 2;
                bh[nt][0] = *(const uint32_t*)(sB_h + e);
                bh[nt][1] = *(const uint32_t*)(sB_h + e + 8);
                bl[nt][0] = *(const uint32_t*)(sB_l + e);
                bl[nt][1] = *(const uint32_t*)(sB_l + e + 8);
            }
            // three passes; within a pass all 16 MMAs independent (hide acc latency)
#pragma unroll
            for (int mt = 0; mt < 4; mt++)
#pragma unroll
                for (int nt = 0; nt < 4; nt++) MMA_BF16(acc[mt][nt], ah[mt], bh[nt]);
#pragma unroll
            for (int mt = 0; mt < 4; mt++)
#pragma unroll
                for (int nt = 0; nt < 4; nt++) MMA_BF16(acc[mt][nt], ah[mt], bl[nt]);
#pragma unroll
            for (int mt = 0; mt < 4; mt++)
#pragma unroll
                for (int nt = 0; nt < 4; nt++) MMA_BF16(acc[mt][nt], al[mt], bh[nt]);
        }
        __syncthreads();
    }

    // epilogue: bias + store fp32
#pragma unroll
    for (int nt = 0; nt < 4; nt++) {
        int ce = col0 + wn * 32 + nt * 8 + t * 2;
        float b0 = bias[ce], b1 = bias[ce + 1];
#pragma unroll
        for (int mt = 0; mt < 4; mt++) {
            int re = row0 + wm * 64 + mt * 16 + g;
            float* p0 = C + (size_t)re * NT + ce;
            p0[0] = acc[mt][nt][0] + b0;
            p0[1] = acc[mt][nt][1] + b1;
            float* p1 = p0 + (size_t)8 * NT;
            p1[0] = acc[mt][nt][2] + b0;
            p1[1] = acc[mt][nt][3] + b1;
        }
    }
}

// ---------------- attention: gather (roll+window) -> softmax -> scatter -----
__global__ __launch_bounds__(128) void attn_kernel() {
    const int m    = blockIdx.x;
    const int head = blockIdx.y;
    __shared__ float qs[VTOK][HDI];
    __shared__ float ks[VTOK][HDI];
    __shared__ float vs[VTOK][HDI];
    __shared__ float ss[VTOK][VTOK];
    __shared__ int   rid[VTOK];
    __shared__ int   pix[VTOK];

    const int tid = threadIdx.x;
    if (tid < VTOK) {
        int wi = m & 63;
        int i  = (wi >> 3) * WSZ + tid / WSZ;
        int j  = (wi & 7)  * WSZ + tid % WSZ;
        rid[tid] = ((i < 45) ? 2 : 0) + ((j < 45) ? 1 : 0);
        int b = m >> 6;
        int h = (i < 45) ? i + 3 : i - 45;
        int w = (j < 45) ? j + 3 : j - 45;
        pix[tid] = (b * HW + h) * HW + w;
    }
    __syncthreads();

    for (int idx = tid; idx < 3 * VTOK * 12; idx += 128) {
        int t3  = idx / (VTOK * 12);
        int rem = idx - t3 * (VTOK * 12);
        int r = rem / 12;
        int c = rem - r * 12;
        float4 f = *(const float4*)(g_qkv + (size_t)pix[r] * D3 + t3 * DIM + head * HDI + c * 4);
        float* dst = (t3 == 0) ? &qs[r][c * 4] : (t3 == 1) ? &ks[r][c * 4] : &vs[r][c * 4];
        *(float4*)dst = f;
    }
    __syncthreads();

    for (int idx = tid; idx < VTOK * VTOK; idx += 128) {
        int v = idx / VTOK;
        int u = idx - v * VTOK;
        float acc = 0.f;
#pragma unroll
        for (int c = 0; c < 12; c++) {
            float4 a = *(float4*)&qs[v][c * 4];
            float4 b = *(float4*)&ks[u][c * 4];
            acc += a.x * b.x + a.y * b.y + a.z * b.z + a.w * b.w;
        }
        ss[v][u] = (rid[v] == rid[u]) ? acc * SCALE : -1e30f;
    }
    __syncthreads();

    if (tid < VTOK) {
        float mx = -1e30f;
#pragma unroll
        for (int u = 0; u < VTOK; u++) mx = fmaxf(mx, ss[tid][u]);
        float sum = 0.f;
#pragma unroll
        for (int u = 0; u < VTOK; u++) {
            float e = __expf(ss[tid][u] - mx);
            ss[tid][u] = e;
            sum += e;
        }
        float inv = 1.f / sum;
#pragma unroll
        for (int u = 0; u < VTOK; u++) ss[tid][u] *= inv;
    }
    __syncthreads();

    for (int idx = tid; idx < VTOK * 12; idx += 128) {
        int v = idx / 12;
        int c = idx - v * 12;
        float4 acc = make_float4(0.f, 0.f, 0.f, 0.f);
#pragma unroll
        for (int u = 0; u < VTOK; u++) {
            float  p  = ss[v][u];
            float4 vv = *(float4*)&vs[u][c * 4];
            acc.x += p * vv.x; acc.y += p * vv.y;
            acc.z += p * vv.z; acc.w += p * vv.w;
        }
        size_t o = (size_t)pix[v] * DIM + head * HDI + c * 4;
        uint16_t h0, h1, h2, h3, l0, l1, l2, l3;
        split2(acc.x, h0, l0); split2(acc.y, h1, l1);
        split2(acc.z, h2, l2); split2(acc.w, h3, l3);
        uint2 H, L;
        H.x = (uint32_t)h0 | ((uint32_t)h1 << 16);
        H.y = (uint32_t)h2 | ((uint32_t)h3 << 16);
        L.x = (uint32_t)l0 | ((uint32_t)l1 << 16);
        L.y = (uint32_t)l2 | ((uint32_t)l3 << 16);
        *(uint2*)(g_att_hi + o) = H;
        *(uint2*)(g_att_lo + o) = L;
    }
}

extern "C" void kernel_launch(void* const* d_in, const int* in_sizes, int n_in,
                              void* d_out, int out_size) {
    const float* x      = (const float*)d_in[0];
    const float* w_qkv  = (const float*)d_in[1];
    const float* b_qkv  = (const float*)d_in[2];
    const float* w_proj = (const float*)d_in[3];
    const float* b_proj = (const float*)d_in[4];
    float* out = (float*)d_out;

    cudaFuncSetAttribute(gemm_bf16<0>, cudaFuncAttributeMaxDynamicSharedMemorySize, 2 * STAGE_B);
    cudaFuncSetAttribute(gemm_bf16<1>, cudaFuncAttributeMaxDynamicSharedMemorySize, 2 * STAGE_B);

    split_x<<<27648, 256>>>(x);                       // 73728*384/4/256
    split_w<D3><<<(KDIM * D3) / 256, 256>>>(w_qkv);
    split_w<DIM><<<(KDIM * DIM) / 256, 256>>>(w_proj);

    gemm_bf16<0><<<dim3(TOK / 128, D3 / 128), 256, 2 * STAGE_B>>>(b_qkv, nullptr);
    attn_kernel<<<dim3(NM, NHE), 128>>>();
    gemm_bf16<1><<<dim3(TOK / 128, DIM / 128), 256, 2 * STAGE_B>>>(b_proj, out);
}